// round 11
// baseline (speedup 1.0000x reference)
#include <cuda_runtime.h>

// Shapes fixed by the dataset:
//   x:                   [N_PTS,  N_NODES] float32
//   learned_edge_states: [N_CMP,  N_NODES] int32 (0 == EDG_NULL)
// Output: concat( new_comp_code [N_PTS,N_CMP] f32, premerge_idx [N_PTS,N_CMP] f32 )
#define N_PTS   256
#define N_NODES 1024
#define N_CMP   1024

#define THR  2.2f     // |x| filter threshold: E[count]=28.5, sd=5.2 for N(0,1)
#define CAP  64       // candidate capacity (P(count>64) ~ 1e-11)

typedef unsigned long long u64;

// Mask bits, CG-MAJOR: d_maskT[cg*1024 + n] bit b == (edges[cg*32+b][n] != 0).
// 128 KB static scratch — L2-resident.
__device__ unsigned d_maskT[(N_CMP / 32) * N_NODES];

// ---------------------------------------------------------------------------
// Kernel 1: pack+transpose, ballot-free and scatter-free (round-10 verified).
// Warp <-> (comp-group cg, 64-node chunk). Lane l owns nodes {2l, 2l+1}:
// registers accumulate transposed bits; one coalesced 256B store per warp.
// ---------------------------------------------------------------------------
__global__ __launch_bounds__(256)
void pack_kernel(const int* __restrict__ edges) {
    const unsigned gw   = (blockIdx.x * blockDim.x + threadIdx.x) >> 5;
    const unsigned lane = threadIdx.x & 31;
    const unsigned cg   = gw & 31;          // component group
    const unsigned nch  = gw >> 5;          // 64-node chunk (16 of them)

    const int2* e2 = (const int2*)edges;
    unsigned w0 = 0, w1 = 0;
    #pragma unroll
    for (int r = 0; r < 32; ++r) {
        int2 v = __ldg(&e2[(cg * 32 + r) * (N_NODES / 2) + nch * 32 + lane]);
        if (v.x) w0 |= 1u << r;
        if (v.y) w1 |= 1u << r;
    }
    ((uint2*)d_maskT)[(cg * N_NODES + nch * 64) / 2 + lane] = make_uint2(w0, w1);
}

// ---------------------------------------------------------------------------
// Kernel 2: sortless. filter -> stage mask words per candidate -> max-reduce.
// Key: (bits(|x|) << 10) | (1023 - n) -> max key == max value, min index.
// 2 blocks per point (h = comp half), 256 threads, 2 comps/thread.
// ---------------------------------------------------------------------------
__device__ __forceinline__ u64 u64max(u64 a, u64 b) { return a > b ? a : b; }

// Exact per-component scan (rare path; overflow / below-threshold / empty).
__device__ __forceinline__ void exact_scan(const float* __restrict__ x,
                                           int p, unsigned cg, unsigned bit,
                                           float& code, float& fidx) {
    u64 best = 0; bool has = false;
    for (int n = 0; n < N_NODES; ++n) {
        unsigned mw = __ldg(&d_maskT[cg * N_NODES + n]);
        if ((mw >> bit) & 1u) {
            float xn = __ldg(&x[p * N_NODES + n]);
            u64 k = (((u64)__float_as_uint(fabsf(xn))) << 10)
                    | (unsigned)((N_NODES - 1) - n);
            if (!has || k > best) { best = k; has = true; }
        }
    }
    if (has) {
        code = __uint_as_float((unsigned)(best >> 10));
        fidx = (float)((N_NODES - 1) - (int)(best & 1023ull));
    } else {
        code = 0.0f; fidx = 0.0f;
    }
}

__global__ __launch_bounds__(256)
void filter_probe_kernel(const float* __restrict__ x,
                         float* __restrict__ out_code,
                         float* __restrict__ out_idx) {
    __shared__ u64 s_cand[CAP];                       // candidate keys (0.5 KB)
    __shared__ __align__(16) unsigned s_w[16 * CAP];  // words[cg_local][cand] (4 KB)
    __shared__ int s_cnt;

    const int p    = blockIdx.x >> 1;     // point
    const int h    = blockIdx.x & 1;      // comp half (512 comps)
    const int t    = threadIdx.x;
    const int w    = t >> 5;
    const int lane = t & 31;

    if (t == 0) s_cnt = 0;
    __syncthreads();

    // ---- filter: 4 consecutive elements per thread (one float4) ----
    float4 xv = __ldg(&((const float4*)(x + p * N_NODES))[t]);
    {
        float a[4] = {xv.x, xv.y, xv.z, xv.w};
        #pragma unroll
        for (int e = 0; e < 4; ++e) {
            float    av   = fabsf(a[e]);
            int      n    = 4 * t + e;
            bool     pred = (av > THR);
            unsigned bal  = __ballot_sync(0xFFFFFFFFu, pred);
            int base = 0;
            if (lane == 0 && bal) base = atomicAdd(&s_cnt, __popc(bal));
            base = __shfl_sync(0xFFFFFFFFu, base, 0);
            if (pred) {
                int pos = base + __popc(bal & ((1u << lane) - 1u));
                if (pos < CAP) {
                    s_cand[pos] = (((u64)__float_as_uint(av)) << 10)
                                  | (unsigned)((N_NODES - 1) - n);
                }
            }
        }
    }
    __syncthreads();

    const int  cnt = s_cnt;
    const bool ovf = (cnt > CAP);         // block-uniform; P ~ 1e-11

    if (!ovf) {
        // ---- stage: warp w serves local cgs {2w, 2w+1}; lane stages
        //      candidates lane and lane+32 (zero-fill beyond cnt) ----
        #pragma unroll
        for (int s = 0; s < 2; ++s) {
            int kk = lane + s * 32;
            unsigned wa = 0, wb = 0;
            if (kk < cnt) {
                int nl = (N_NODES - 1) - (int)(s_cand[kk] & 1023ull);
                unsigned cgA = (unsigned)(h * 16 + 2 * w);
                wa = __ldg(&d_maskT[cgA * N_NODES + (unsigned)nl]);
                wb = __ldg(&d_maskT[(cgA + 1) * N_NODES + (unsigned)nl]);
            }
            s_w[(2 * w)     * CAP + kk] = wa;
            s_w[(2 * w + 1) * CAP + kk] = wb;
        }
        __syncthreads();

        // ---- max-reduce over candidates (no sort, no priority needed) ----
        const unsigned cg0 = (unsigned)t >> 5;        // local cg of comp t
        const unsigned cg1 = cg0 + 8;                 // local cg of comp t+256
        const unsigned bit = (unsigned)t & 31;        // same for both comps

        u64 best0 = 0, best1 = 0;
        #pragma unroll 4
        for (int kk = 0; kk < cnt; ++kk) {
            u64      key = s_cand[kk];                // broadcast LDS.64
            unsigned w0  = s_w[cg0 * CAP + kk];       // broadcast LDS
            unsigned w1  = s_w[cg1 * CAP + kk];
            if ((w0 >> bit) & 1u) best0 = u64max(best0, key);
            if ((w1 >> bit) & 1u) best1 = u64max(best1, key);
        }

        const int c0 = h * 512 + t;
        const int c1 = c0 + 256;

        float code0, fidx0, code1, fidx1;
        if (best0) {
            code0 = __uint_as_float((unsigned)(best0 >> 10));
            fidx0 = (float)((N_NODES - 1) - (int)(best0 & 1023ull));
        } else {
            exact_scan(x, p, (unsigned)c0 >> 5, bit, code0, fidx0);
        }
        if (best1) {
            code1 = __uint_as_float((unsigned)(best1 >> 10));
            fidx1 = (float)((N_NODES - 1) - (int)(best1 & 1023ull));
        } else {
            exact_scan(x, p, (unsigned)c1 >> 5, bit, code1, fidx1);
        }

        out_code[p * N_CMP + c0] = code0;
        out_idx [p * N_CMP + c0] = fidx0;
        out_code[p * N_CMP + c1] = code1;
        out_idx [p * N_CMP + c1] = fidx1;
    } else {
        // overflow: exact path for every comp this thread owns
        #pragma unroll
        for (int half = 0; half < 2; ++half) {
            const int      c   = h * 512 + t + half * 256;
            const unsigned cg  = (unsigned)c >> 5;
            const unsigned bit = (unsigned)c & 31;
            float code, fidx;
            exact_scan(x, p, cg, bit, code, fidx);
            out_code[p * N_CMP + c] = code;
            out_idx [p * N_CMP + c] = fidx;
        }
    }
}

// ---------------------------------------------------------------------------
extern "C" void kernel_launch(void* const* d_in, const int* in_sizes, int n_in,
                              void* d_out, int out_size) {
    const float* x     = (const float*)d_in[0];
    const int*   edges = (const int*)  d_in[1];
    float*       out   = (float*)d_out;

    // 512 warps: 64 blocks x 256 threads (32 cg * 16 node-chunks)
    pack_kernel<<<64, 256>>>(edges);
    // 2 blocks per point x 256 threads
    filter_probe_kernel<<<N_PTS * 2, 256>>>(x, out, out + (size_t)N_PTS * N_CMP);
}

// round 14
// speedup vs baseline: 1.3798x; 1.3798x over previous
#include <cuda_runtime.h>

// Shapes fixed by the dataset:
//   x:                   [N_PTS,  N_NODES] float32
//   learned_edge_states: [N_CMP,  N_NODES] int32 (0 == EDG_NULL)
// Output: concat( new_comp_code [N_PTS,N_CMP] f32, premerge_idx [N_PTS,N_CMP] f32 )
#define N_PTS   256
#define N_NODES 1024
#define N_CMP   1024

#define THR  2.2f     // |x| filter threshold: E[count]=28.5, sd=5.2 for N(0,1)
#define CAP  64       // candidate capacity (P(count>64) ~ 1e-11)

#define PACK_BLOCKS 32

typedef unsigned long long u64;

// Mask bits, CG-MAJOR: d_maskT[cg*1024 + n] bit b == (edges[cg*32+b][n] != 0).
// Written during the kernel -> consumers use __ldcg / atomics, never __ldg.
__device__ unsigned d_maskT[(N_CMP / 32) * N_NODES];   // 128 KB, L2-resident
// Pack-done flags (zero-initialized). Sticky across graph replays is safe:
// pack rewrites identical data, so early readers see identical bits.
__device__ int d_done[PACK_BLOCKS];

__device__ __forceinline__ u64 u64max(u64 a, u64 b) { return a > b ? a : b; }
__device__ __forceinline__ u64 u64min(u64 a, u64 b) { return a < b ? a : b; }

// Exact per-component scan (rare path; overflow / below-threshold / empty).
__device__ __forceinline__ void exact_scan(const float* __restrict__ x,
                                           int p, unsigned cg, unsigned bit,
                                           float& code, float& fidx) {
    u64 best = 0; bool has = false;
    for (int n = 0; n < N_NODES; ++n) {
        unsigned mw = __ldcg(&d_maskT[cg * N_NODES + n]);
        if ((mw >> bit) & 1u) {
            float xn = __ldg(&x[p * N_NODES + n]);
            u64 k = (((u64)__float_as_uint(fabsf(xn))) << 10)
                    | (unsigned)((N_NODES - 1) - n);
            if (!has || k > best) { best = k; has = true; }
        }
    }
    if (has) {
        code = __uint_as_float((unsigned)(best >> 10));
        fidx = (float)((N_NODES - 1) - (int)(best & 1023ull));
    } else {
        code = 0.0f; fidx = 0.0f;
    }
}

// Consumer-side wait: warp 1 spins on all pack flags (atomic polls cannot be
// hoisted and are L2-coherent), then a cumulative acquire fence, then the
// block-wide bar orders every thread's subsequent maskT loads.
__device__ __forceinline__ void wait_for_pack(int w, int lane) {
    if (w == 1 && lane < PACK_BLOCKS) {
        while (atomicAdd(&d_done[lane], 0) == 0) { }
        __threadfence();   // acquire (cumulative): maskT loads ordered after
    }
    __syncthreads();
}

// ---------------------------------------------------------------------------
// Fused kernel. Blocks [0,32): pack. Blocks [32,288): per-point filter ->
// warp0 top-32 sort -> wait-for-pack -> stage -> flat hitmask probe.
// Key: (bits(|x|) << 10) | (1023 - n) -> max key == max value, min index.
// ---------------------------------------------------------------------------
__global__ __launch_bounds__(512)
void fused_kernel(const float* __restrict__ x,
                  const int* __restrict__ edges,
                  float* __restrict__ out_code,
                  float* __restrict__ out_idx) {
    const int t    = threadIdx.x;
    const int w    = t >> 5;
    const int lane = t & 31;

    if (blockIdx.x < PACK_BLOCKS) {
        // ================= PACK (verified round-10 layout) =================
        const unsigned gw  = blockIdx.x * 16 + (unsigned)w;
        const unsigned cg  = gw & 31;
        const unsigned nch = gw >> 5;

        const int2* e2 = (const int2*)edges;
        unsigned w0 = 0, w1 = 0;
        #pragma unroll
        for (int r = 0; r < 32; ++r) {
            int2 v = __ldg(&e2[(cg * 32 + r) * (N_NODES / 2) + nch * 32 + lane]);
            if (v.x) w0 |= 1u << r;
            if (v.y) w1 |= 1u << r;
        }
        ((uint2*)d_maskT)[(cg * N_NODES + nch * 64) / 2 + lane] =
            make_uint2(w0, w1);

        // Cumulative release: bar makes all threads' stores happen-before
        // t0's fence (CTA scope); t0's fence.gpu then promotes THEM to GPU
        // scope before the morally-strong flag publish.
        __syncthreads();
        if (t == 0) {
            __threadfence();
            atomicExch(&d_done[blockIdx.x], 1);
        }
        return;
    }

    // ======================= FILTER + SORT + PROBE =========================
    __shared__ u64 s_cand[CAP];
    __shared__ u64 s_top[32];
    __shared__ __align__(16) unsigned s_w[32 * 32];  // rank-words per cg (4 KB)
    __shared__ int s_cnt;

    const int p = blockIdx.x - PACK_BLOCKS;

    if (t == 0) s_cnt = 0;
    __syncthreads();

    // ---- filter: 2 consecutive elements/thread, ONE shared atomic/warp ----
    float2 xv = __ldg(&((const float2*)(x + p * N_NODES))[t]);
    {
        float a0 = fabsf(xv.x), a1 = fabsf(xv.y);
        bool  p0 = (a0 > THR),  p1 = (a1 > THR);
        unsigned bal0 = __ballot_sync(0xFFFFFFFFu, p0);
        unsigned bal1 = __ballot_sync(0xFFFFFFFFu, p1);
        int tot = __popc(bal0) + __popc(bal1);
        int base = 0;
        if (lane == 0 && tot) base = atomicAdd(&s_cnt, tot);
        base = __shfl_sync(0xFFFFFFFFu, base, 0);
        unsigned below = (1u << lane) - 1u;
        if (p0) {
            int pos = base + __popc(bal0 & below);
            if (pos < CAP)
                s_cand[pos] = (((u64)__float_as_uint(a0)) << 10)
                              | (unsigned)((N_NODES - 1) - (2 * t));
        }
        if (p1) {
            int pos = base + __popc(bal0) + __popc(bal1 & below);
            if (pos < CAP)
                s_cand[pos] = (((u64)__float_as_uint(a1)) << 10)
                              | (unsigned)((N_NODES - 1) - (2 * t + 1));
        }
    }
    __syncthreads();

    const int  cnt = s_cnt;
    const bool ovf = (cnt > CAP);        // block-uniform; P ~ 1e-11

    if (!ovf) {
        // ---- warp 0: dual bitonic sort + merge -> top-32 descending ----
        if (w == 0) {
            u64 k1 = (lane      < cnt) ? s_cand[lane]      : 0ull;
            u64 k2 = (lane + 32 < cnt) ? s_cand[lane + 32] : 0ull;
            #pragma unroll
            for (int k = 2; k <= 32; k <<= 1) {
                #pragma unroll
                for (int j = k >> 1; j > 0; j >>= 1) {
                    bool dirUp = ((lane & k) == 0);
                    bool lower = ((lane & j) == 0);
                    u64 o1 = __shfl_xor_sync(0xFFFFFFFFu, k1, j);
                    u64 o2 = __shfl_xor_sync(0xFFFFFFFFu, k2, j);
                    k1 = (dirUp == lower) ? u64min(k1, o1) : u64max(k1, o1);
                    k2 = (dirUp == lower) ? u64min(k2, o2) : u64max(k2, o2);
                }
            }
            u64 a = __shfl_xor_sync(0xFFFFFFFFu, k1, 31);   // descending
            u64 m = u64max(a, k2);                          // bitonic top-32
            #pragma unroll
            for (int j = 16; j > 0; j >>= 1) {              // -> descending
                u64 o = __shfl_xor_sync(0xFFFFFFFFu, m, j);
                bool lower = ((lane & j) == 0);
                m = lower ? u64max(m, o) : u64min(m, o);
            }
            s_top[lane] = m;
        }

        // ---- wait for pack (overlaps: sort above ran during pack) ----
        wait_for_pack(w, lane);

        const int n_valid = cnt < 32 ? cnt : 32;
        const unsigned vmask =
            (n_valid >= 32) ? 0xFFFFFFFFu : ((1u << n_valid) - 1u);

        // ---- stage: lane kk loads mask word for top-kk node; warp w serves
        //      comp-groups w and w+16 (cg-major layout, L2-coherent) ----
        {
            u64 keyl = s_top[lane];
            int  nl  = (N_NODES - 1) - (int)(keyl & 1023ull);
            s_w[w * 32 + lane] =
                __ldcg(&d_maskT[(unsigned)w * N_NODES + (unsigned)nl]);
            s_w[(w + 16) * 32 + lane] =
                __ldcg(&d_maskT[(unsigned)(w + 16) * N_NODES + (unsigned)nl]);
        }
        __syncthreads();

        // ---- flat probe: 32-bit hitmask from 8 broadcast uint4 LDS ----
        #pragma unroll
        for (int half = 0; half < 2; ++half) {
            const int      c   = t + half * 512;
            const unsigned cg  = (unsigned)c >> 5;     // warp-uniform
            const unsigned bit = (unsigned)c & 31;

            const uint4* row = (const uint4*)&s_w[cg * 32];
            unsigned hm = 0;
            #pragma unroll
            for (int q = 0; q < 8; ++q) {
                uint4 u = row[q];                      // broadcast LDS.128
                hm |= ((u.x >> bit) & 1u) << (4 * q + 0);
                hm |= ((u.y >> bit) & 1u) << (4 * q + 1);
                hm |= ((u.z >> bit) & 1u) << (4 * q + 2);
                hm |= ((u.w >> bit) & 1u) << (4 * q + 3);
            }
            hm &= vmask;

            float code, fidx;
            if (hm) {
                int kk = __ffs(hm) - 1;                // best rank with a hit
                u64 k3 = s_top[kk];
                code = __uint_as_float((unsigned)(k3 >> 10));
                fidx = (float)((N_NODES - 1) - (int)(k3 & 1023ull));
            } else {
                exact_scan(x, p, cg, bit, code, fidx);
            }
            out_code[p * N_CMP + c] = code;
            out_idx [p * N_CMP + c] = fidx;
        }
    } else {
        // overflow: wait for pack, then exact path for all owned comps
        wait_for_pack(w, lane);
        #pragma unroll
        for (int half = 0; half < 2; ++half) {
            const int      c   = t + half * 512;
            const unsigned cg  = (unsigned)c >> 5;
            const unsigned bit = (unsigned)c & 31;
            float code, fidx;
            exact_scan(x, p, cg, bit, code, fidx);
            out_code[p * N_CMP + c] = code;
            out_idx [p * N_CMP + c] = fidx;
        }
    }
}

// ---------------------------------------------------------------------------
extern "C" void kernel_launch(void* const* d_in, const int* in_sizes, int n_in,
                              void* d_out, int out_size) {
    const float* x     = (const float*)d_in[0];
    const int*   edges = (const int*)  d_in[1];
    float*       out   = (float*)d_out;

    // 32 pack blocks + 256 probe blocks, all co-resident (4 blocks/SM x 148).
    fused_kernel<<<PACK_BLOCKS + N_PTS, 512>>>(
        x, edges, out, out + (size_t)N_PTS * N_CMP);
}